// round 8
// baseline (speedup 1.0000x reference)
#include <cuda_runtime.h>
#include <cstdint>

#define TT 512
#define BB 64
#define HH 512
#define GG 2048
#define TB (TT*BB)
#define NBLK 128

__device__ __align__(16) float g_xbuf[2][(size_t)TB * 1024];
__device__ __align__(16) float g_gx[2][(size_t)TB * GG];
__device__ __align__(16) float g_h[2][2][BB * HH];
__device__ __align__(16) float g_c[2][BB * HH];
__device__ int g_len[BB];
__device__ unsigned g_bar;

__device__ __forceinline__ float to_tf32(float x) {
    asm("cvt.rna.tf32.f32 %0, %0;" : "+f"(x));
    return x;
}
__device__ __forceinline__ void cvt4(float4& v) {
    v.x = to_tf32(v.x); v.y = to_tf32(v.y); v.z = to_tf32(v.z); v.w = to_tf32(v.w);
}
__device__ __forceinline__ void mma_tf32(float4& d, const uint32_t* a, const uint32_t* b) {
    asm volatile(
        "mma.sync.aligned.m16n8k8.row.col.f32.tf32.tf32.f32 "
        "{%0,%1,%2,%3}, {%4,%5,%6,%7}, {%8,%9}, {%0,%1,%2,%3};\n"
        : "+f"(d.x), "+f"(d.y), "+f"(d.z), "+f"(d.w)
        : "r"(a[0]), "r"(a[1]), "r"(a[2]), "r"(a[3]), "r"(b[0]), "r"(b[1]));
}
__device__ __forceinline__ float sigm(float x) { return 1.0f / (1.0f + expf(-x)); }

__global__ void k_len(const int* __restrict__ pack_idx, int NP) {
    __shared__ int cnt[BB];
    int tid = threadIdx.x;
    if (tid < BB) cnt[tid] = 0;
    __syncthreads();
    for (int i = tid; i < NP; i += blockDim.x)
        atomicAdd(&cnt[pack_idx[i] & (BB - 1)], 1);
    __syncthreads();
    if (tid < BB) g_len[tid] = cnt[tid];
}

__global__ void k_scatter(const float* __restrict__ data, const int* __restrict__ pack_idx, int total) {
    int e = blockIdx.x * blockDim.x + threadIdx.x;
    if (e < total) {
        int i = e >> 9, col = e & 511;
        g_xbuf[0][(size_t)pack_idx[i] * 512 + col] = data[e];
    }
}

__global__ void k_gather(float* __restrict__ out, const int* __restrict__ pack_idx, int total) {
    int e = blockIdx.x * blockDim.x + threadIdx.x;
    if (e < total) {
        int i = e >> 10, col = e & 1023;
        out[e] = g_xbuf[1][(size_t)pack_idx[i] * 1024 + col];
    }
}

__global__ void k_init(const float* __restrict__ h0, const float* __restrict__ c0, int l) {
    int idx = blockIdx.x * blockDim.x + threadIdx.x;
    if (idx == 0) g_bar = 0u;
    int dir = idx >> 15, rem = idx & 32767;
    size_t src = (size_t)(2 * l + dir) * 32768 + rem;
    g_h[0][dir][rem] = h0[src];
    g_c[dir][rem]    = c0[src];
}

__global__ void k_save(float* __restrict__ out, int NP, int l) {
    int idx = blockIdx.x * blockDim.x + threadIdx.x;
    int dir = idx >> 15, rem = idx & 32767;
    size_t OH = (size_t)NP * 1024;
    size_t off = (size_t)(2 * l + dir) * 32768 + rem;
    out[OH + off]             = g_h[0][dir][rem];
    out[OH + 6 * 32768 + off] = g_c[dir][rem];
}

// ---------------------------------------------------------------------------
// Input GEMM: gx[dir][m,n] = bias[n] + sum_k X[m,k]*W[n,k]; 128x64x32 tiles
// ---------------------------------------------------------------------------
__global__ __launch_bounds__(256)
void k_gemm_gx(int xsel, int ldx, int K, const float* __restrict__ W,
               const float* __restrict__ bias, int dir) {
    const float* X = g_xbuf[xsel];
    float* out = g_gx[dir];
    __shared__ float Xs[128][36];
    __shared__ float Ws[64][36];
    int tid = threadIdx.x, lane = tid & 31, warp = tid >> 5;
    int wm = warp & 3, wn = warp >> 2;
    int gid = lane >> 2, tig = lane & 3;
    int m0 = blockIdx.x * 128, n0 = blockIdx.y * 64;

    float4 acc[2][4];
#pragma unroll
    for (int mt = 0; mt < 2; mt++)
#pragma unroll
        for (int nt = 0; nt < 4; nt++) acc[mt][nt] = make_float4(0.f, 0.f, 0.f, 0.f);

    for (int k0 = 0; k0 < K; k0 += 32) {
#pragma unroll
        for (int it = 0; it < 4; it++) {
            int idx = it * 256 + tid, r = idx >> 3, kq = idx & 7;
            float4 v = *(const float4*)(X + (size_t)(m0 + r) * ldx + k0 + kq * 4);
            cvt4(v);
            *(float4*)(&Xs[r][kq * 4]) = v;
        }
#pragma unroll
        for (int it = 0; it < 2; it++) {
            int idx = it * 256 + tid, r = idx >> 3, kq = idx & 7;
            float4 v = *(const float4*)(W + (size_t)(n0 + r) * K + k0 + kq * 4);
            cvt4(v);
            *(float4*)(&Ws[r][kq * 4]) = v;
        }
        __syncthreads();
#pragma unroll
        for (int kk = 0; kk < 32; kk += 8) {
            uint32_t a[2][4], b[4][2];
#pragma unroll
            for (int mt = 0; mt < 2; mt++) {
                int mr = wm * 32 + mt * 16;
                a[mt][0] = __float_as_uint(Xs[mr + gid][kk + tig]);
                a[mt][1] = __float_as_uint(Xs[mr + gid + 8][kk + tig]);
                a[mt][2] = __float_as_uint(Xs[mr + gid][kk + tig + 4]);
                a[mt][3] = __float_as_uint(Xs[mr + gid + 8][kk + tig + 4]);
            }
#pragma unroll
            for (int nt = 0; nt < 4; nt++) {
                int nr = wn * 32 + nt * 8;
                b[nt][0] = __float_as_uint(Ws[nr + gid][kk + tig]);
                b[nt][1] = __float_as_uint(Ws[nr + gid][kk + tig + 4]);
            }
#pragma unroll
            for (int mt = 0; mt < 2; mt++)
#pragma unroll
                for (int nt = 0; nt < 4; nt++) mma_tf32(acc[mt][nt], a[mt], b[nt]);
        }
        __syncthreads();
    }
#pragma unroll
    for (int mt = 0; mt < 2; mt++)
#pragma unroll
        for (int nt = 0; nt < 4; nt++) {
            int row = m0 + wm * 32 + mt * 16 + gid;
            int col = n0 + wn * 32 + nt * 8 + tig * 2;
            float bx = bias[col], by = bias[col + 1];
            float* p = out + (size_t)row * GG + col;
            p[0] = acc[mt][nt].x + bx;
            p[1] = acc[mt][nt].y + by;
            p += (size_t)8 * GG;
            p[0] = acc[mt][nt].z + bx;
            p[1] = acc[mt][nt].w + by;
        }
}

// ---------------------------------------------------------------------------
// Persistent recurrent scan: one launch does all 512 timesteps of a layer.
// 128 blocks = 2 dirs x 64 j-tiles(8). W_hh tile resident in SMEM.
// Dynamic smem: Ws[32][516] | Hs[2][64][68] | Gs[64][36]
// ---------------------------------------------------------------------------
#define WS_OFF   0
#define HS_OFF   16512
#define GS_OFF   (16512 + 8704)
#define SCAN_SMEM ((16512 + 8704 + 2304) * 4)

__global__ __launch_bounds__(256)
void k_scan(const float* __restrict__ Whh0, const float* __restrict__ Whh1,
            int xoutsel) {
    extern __shared__ float s[];
    float* Ws = s + WS_OFF;     // [32][516]
    float* Hs = s + HS_OFF;     // [2][64][68]
    float* Gs = s + GS_OFF;     // [64][36]
#define WS(r,c)    Ws[(r)*516 + (c)]
#define HSm(b,r,c) Hs[(b)*4352 + (r)*68 + (c)]
#define GS(r,c)    Gs[(r)*36 + (c)]

    int bid = blockIdx.x;
    int dir = bid >> 6;
    int j0 = (bid & 63) * 8;
    const float* Whh = dir ? Whh1 : Whh0;
    float* cbuf = g_c[dir];
    const float* gx = g_gx[dir];
    float* xout = g_xbuf[xoutsel];

    int tid = threadIdx.x, lane = tid & 31, warp = tid >> 5;
    int wm = warp & 3, wn = warp >> 2;        // 4(m) x 2(n)
    int gid = lane >> 2, tig = lane & 3;

    // load W tile once: 32 gate cols (4 quadrants x 8 j) x 512 k
#pragma unroll
    for (int it = 0; it < 16; it++) {
        int idx = it * 256 + tid;             // float4 index
        int gc = idx >> 7, cq = idx & 127;
        int gr = (gc >> 3) * HH + j0 + (gc & 7);
        float4 v = *(const float4*)(Whh + (size_t)gr * HH + cq * 4);
        cvt4(v);
        *(float4*)&WS(gc, cq * 4) = v;
    }
    __syncthreads();

    // per-thread elementwise cell assignments (fixed across steps)
    int cb[2], cjj[2], clb[2], cbj[2];
#pragma unroll
    for (int it = 0; it < 2; it++) {
        int cell = it * 256 + tid;
        cb[it] = cell >> 3;
        cjj[it] = cell & 7;
        clb[it] = g_len[cb[it]];
        cbj[it] = cb[it] * HH + j0 + cjj[it];
    }

    for (int t = 0; t < TT; t++) {
        int p = t & 1;
        const float* hcur = g_h[p][dir];
        float* hnext = g_h[p ^ 1][dir];

        // preload h chunk 0 (L2, bypass L1 — other blocks wrote it)
#pragma unroll
        for (int it = 0; it < 4; it++) {
            int idx = it * 256 + tid, r = idx >> 4, cq = idx & 15;
            float4 v = __ldcg((const float4*)(hcur + r * HH + cq * 4));
            cvt4(v);
            *(float4*)&HSm(0, r, cq * 4) = v;
        }
        __syncthreads();

        float4 acc0 = make_float4(0.f, 0.f, 0.f, 0.f);
        float4 acc1 = make_float4(0.f, 0.f, 0.f, 0.f);

        for (int ch = 0; ch < 8; ch++) {
            float4 pre[4];
            if (ch < 7) {
                int k0 = (ch + 1) * 64;
#pragma unroll
                for (int it = 0; it < 4; it++) {
                    int idx = it * 256 + tid, r = idx >> 4, cq = idx & 15;
                    pre[it] = __ldcg((const float4*)(hcur + r * HH + k0 + cq * 4));
                }
            }
            int bf = ch & 1;
            int kc = ch * 64;
#pragma unroll
            for (int kk = 0; kk < 64; kk += 8) {
                uint32_t a[4];
                int mr = wm * 16;
                a[0] = __float_as_uint(HSm(bf, mr + gid, kk + tig));
                a[1] = __float_as_uint(HSm(bf, mr + gid + 8, kk + tig));
                a[2] = __float_as_uint(HSm(bf, mr + gid, kk + tig + 4));
                a[3] = __float_as_uint(HSm(bf, mr + gid + 8, kk + tig + 4));
                int nr = wn * 16;
                uint32_t b0[2] = { __float_as_uint(WS(nr + gid, kc + kk + tig)),
                                   __float_as_uint(WS(nr + gid, kc + kk + tig + 4)) };
                mma_tf32(acc0, a, b0);
                uint32_t b1[2] = { __float_as_uint(WS(nr + 8 + gid, kc + kk + tig)),
                                   __float_as_uint(WS(nr + 8 + gid, kc + kk + tig + 4)) };
                mma_tf32(acc1, a, b1);
            }
            if (ch < 7) {
#pragma unroll
                for (int it = 0; it < 4; it++) {
                    int idx = it * 256 + tid, r = idx >> 4, cq = idx & 15;
                    cvt4(pre[it]);
                    *(float4*)&HSm((ch + 1) & 1, r, cq * 4) = pre[it];
                }
            }
            __syncthreads();
        }

        // spill gate pre-acts
        {
            int row = wm * 16 + gid;
            int col = wn * 16 + tig * 2;
            GS(row, col)         = acc0.x; GS(row, col + 1)         = acc0.y;
            GS(row + 8, col)     = acc0.z; GS(row + 8, col + 1)     = acc0.w;
            GS(row, col + 8)     = acc1.x; GS(row, col + 9)         = acc1.y;
            GS(row + 8, col + 8) = acc1.z; GS(row + 8, col + 9)     = acc1.w;
        }
        __syncthreads();

        // elementwise LSTM update: 64 b x 8 j = 512 cells, 2 per thread
#pragma unroll
        for (int it = 0; it < 2; it++) {
            int b = cb[it], jj = cjj[it], lb = clb[it], bj = cbj[it];
            int j = j0 + jj;
            if (t < lb) {
                int r = dir ? ((lb - 1 - t) * BB + b) : (t * BB + b);
                const float* gxr = gx + (size_t)r * GG;
                float iv = GS(b, jj)      + gxr[j];
                float fv = GS(b, 8 + jj)  + gxr[512 + j];
                float gv = GS(b, 16 + jj) + gxr[1024 + j];
                float ov = GS(b, 24 + jj) + gxr[1536 + j];
                float cn = sigm(fv) * cbuf[bj] + sigm(iv) * tanhf(gv);
                float hn = sigm(ov) * tanhf(cn);
                cbuf[bj] = cn;
                hnext[bj] = hn;
                int tout = dir ? (lb - 1 - t) : t;
                xout[(size_t)(tout * BB + b) * 1024 + dir * HH + j] = hn;
            } else {
                hnext[bj] = __ldcg(hcur + bj);
            }
        }

        // grid-wide barrier (release/acquire; bar.sync cumulativity covers
        // all threads' stores)
        __syncthreads();
        if (tid == 0) {
            unsigned target = (unsigned)NBLK * (unsigned)(t + 1);
            asm volatile("red.release.gpu.global.add.u32 [%0], %1;"
                         :: "l"(&g_bar), "r"(1u) : "memory");
            unsigned v;
            do {
                asm volatile("ld.acquire.gpu.global.u32 %0, [%1];"
                             : "=r"(v) : "l"(&g_bar) : "memory");
            } while (v < target);
        }
        __syncthreads();
    }
#undef WS
#undef HSm
#undef GS
}

extern "C" void kernel_launch(void* const* d_in, const int* in_sizes, int n_in,
                              void* d_out, int out_size) {
    const float* data   = (const float*)d_in[0];
    const float* h0     = (const float*)d_in[1];
    const float* c0     = (const float*)d_in[2];
    const float* w_ih0  = (const float*)d_in[3];
    const float* w_hh0  = (const float*)d_in[4];
    const float* b0     = (const float*)d_in[5];
    const float* w_ih_r = (const float*)d_in[6];
    const float* w_hh_r = (const float*)d_in[7];
    const float* b_r    = (const float*)d_in[8];
    const int*   pack   = (const int*)d_in[10];

    const int NP = in_sizes[0] / 512;
    float* out = (float*)d_out;

    static int smem_set = 0;
    if (!smem_set) {
        cudaFuncSetAttribute(k_scan, cudaFuncAttributeMaxDynamicSharedMemorySize,
                             SCAN_SMEM);
        smem_set = 1;
    }

    k_len<<<1, 1024>>>(pack, NP);
    k_scatter<<<(NP * 512 + 255) / 256, 256>>>(data, pack, NP * 512);

    const int LX[3]  = {0, 1, 0};
    const int LLD[3] = {512, 1024, 1024};
    const int LK[3]  = {512, 1024, 1024};
    const int LO[3]  = {1, 0, 1};

    for (int l = 0; l < 3; l++) {
        for (int d = 0; d < 2; d++) {
            const float* Wih = (l == 0)
                ? w_ih0 + (size_t)d * GG * 512
                : w_ih_r + (size_t)((l - 1) * 2 + d) * GG * 1024;
            const float* bs = (l == 0)
                ? b0 + (size_t)d * GG
                : b_r + (size_t)((l - 1) * 2 + d) * GG;
            k_gemm_gx<<<dim3(TB / 128, GG / 64), 256>>>(LX[l], LLD[l], LK[l], Wih, bs, d);
        }
        k_init<<<256, 256>>>(h0, c0, l);

        const float* W0 = (l == 0) ? w_hh0
                                   : w_hh_r + (size_t)((l - 1) * 2 + 0) * GG * HH;
        const float* W1 = (l == 0) ? w_hh0 + (size_t)GG * HH
                                   : w_hh_r + (size_t)((l - 1) * 2 + 1) * GG * HH;
        k_scan<<<NBLK, 256, SCAN_SMEM>>>(W0, W1, LO[l]);

        k_save<<<256, 256>>>(out, NP, l);
    }
    k_gather<<<(NP * 1024 + 255) / 256, 256>>>(out, pack, NP * 1024);
}

// round 12
// speedup vs baseline: 1.2403x; 1.2403x over previous
#include <cuda_runtime.h>
#include <cstdint>

#define TT 512
#define BB 64
#define HH 512
#define GG 2048
#define TB (TT*BB)

__device__ __align__(16) float g_xbuf[2][(size_t)TB * 1024];
__device__ __align__(16) float g_gx[2][(size_t)TB * GG];
__device__ __align__(16) float g_h[2][2][BB * HH];
__device__ __align__(16) float g_c[2][BB * HH];
__device__ int g_len[BB];
__device__ unsigned g_bar2[2][32];

__device__ __forceinline__ float to_tf32(float x) {
    asm("cvt.rna.tf32.f32 %0, %0;" : "+f"(x));
    return x;
}
__device__ __forceinline__ void cvt4(float4& v) {
    v.x = to_tf32(v.x); v.y = to_tf32(v.y); v.z = to_tf32(v.z); v.w = to_tf32(v.w);
}
__device__ __forceinline__ void mma_tf32(float4& d, const uint32_t* a, const uint32_t* b) {
    asm volatile(
        "mma.sync.aligned.m16n8k8.row.col.f32.tf32.tf32.f32 "
        "{%0,%1,%2,%3}, {%4,%5,%6,%7}, {%8,%9}, {%0,%1,%2,%3};\n"
        : "+f"(d.x), "+f"(d.y), "+f"(d.z), "+f"(d.w)
        : "r"(a[0]), "r"(a[1]), "r"(a[2]), "r"(a[3]), "r"(b[0]), "r"(b[1]));
}
__device__ __forceinline__ float sigm(float x) { return 1.0f / (1.0f + expf(-x)); }
__device__ __forceinline__ void cp_async16(uint32_t saddr, const void* gaddr) {
    asm volatile("cp.async.cg.shared.global [%0], [%1], 16;\n"
                 :: "r"(saddr), "l"(gaddr));
}

__global__ void k_len(const int* __restrict__ pack_idx, int NP) {
    __shared__ int cnt[BB];
    int tid = threadIdx.x;
    if (tid < BB) cnt[tid] = 0;
    __syncthreads();
    for (int i = tid; i < NP; i += blockDim.x)
        atomicAdd(&cnt[pack_idx[i] & (BB - 1)], 1);
    __syncthreads();
    if (tid < BB) g_len[tid] = cnt[tid];
}

__global__ void k_scatter(const float* __restrict__ data, const int* __restrict__ pack_idx, int total) {
    int e = blockIdx.x * blockDim.x + threadIdx.x;
    if (e < total) {
        int i = e >> 9, col = e & 511;
        g_xbuf[0][(size_t)pack_idx[i] * 512 + col] = data[e];
    }
}

__global__ void k_gather(float* __restrict__ out, const int* __restrict__ pack_idx, int total) {
    int e = blockIdx.x * blockDim.x + threadIdx.x;
    if (e < total) {
        int i = e >> 10, col = e & 1023;
        out[e] = g_xbuf[1][(size_t)pack_idx[i] * 1024 + col];
    }
}

// h state is stored TF32-rounded (consumed raw by mma); c stays full fp32.
__global__ void k_init(const float* __restrict__ h0, const float* __restrict__ c0, int l) {
    int idx = blockIdx.x * blockDim.x + threadIdx.x;
    if (idx < 2) g_bar2[idx][0] = 0u;
    int dir = idx >> 15, rem = idx & 32767;
    size_t src = (size_t)(2 * l + dir) * 32768 + rem;
    g_h[0][dir][rem] = to_tf32(h0[src]);
    g_c[dir][rem]    = c0[src];
}

__global__ void k_save(float* __restrict__ out, int NP, int l) {
    int idx = blockIdx.x * blockDim.x + threadIdx.x;
    int dir = idx >> 15, rem = idx & 32767;
    size_t OH = (size_t)NP * 1024;
    size_t off = (size_t)(2 * l + dir) * 32768 + rem;
    out[OH + off]             = g_h[0][dir][rem];
    out[OH + 6 * 32768 + off] = g_c[dir][rem];
}

// ---------------------------------------------------------------------------
// Input GEMM (unchanged from R8): gx[m,n] = bias[n] + sum_k X[m,k]*W[n,k]
// ---------------------------------------------------------------------------
__global__ __launch_bounds__(256)
void k_gemm_gx(int xsel, int ldx, int K, const float* __restrict__ W,
               const float* __restrict__ bias, int dir) {
    const float* X = g_xbuf[xsel];
    float* out = g_gx[dir];
    __shared__ float Xs[128][36];
    __shared__ float Ws[64][36];
    int tid = threadIdx.x, lane = tid & 31, warp = tid >> 5;
    int wm = warp & 3, wn = warp >> 2;
    int gid = lane >> 2, tig = lane & 3;
    int m0 = blockIdx.x * 128, n0 = blockIdx.y * 64;

    float4 acc[2][4];
#pragma unroll
    for (int mt = 0; mt < 2; mt++)
#pragma unroll
        for (int nt = 0; nt < 4; nt++) acc[mt][nt] = make_float4(0.f, 0.f, 0.f, 0.f);

    for (int k0 = 0; k0 < K; k0 += 32) {
#pragma unroll
        for (int it = 0; it < 4; it++) {
            int idx = it * 256 + tid, r = idx >> 3, kq = idx & 7;
            float4 v = *(const float4*)(X + (size_t)(m0 + r) * ldx + k0 + kq * 4);
            cvt4(v);
            *(float4*)(&Xs[r][kq * 4]) = v;
        }
#pragma unroll
        for (int it = 0; it < 2; it++) {
            int idx = it * 256 + tid, r = idx >> 3, kq = idx & 7;
            float4 v = *(const float4*)(W + (size_t)(n0 + r) * K + k0 + kq * 4);
            cvt4(v);
            *(float4*)(&Ws[r][kq * 4]) = v;
        }
        __syncthreads();
#pragma unroll
        for (int kk = 0; kk < 32; kk += 8) {
            uint32_t a[2][4], b[4][2];
#pragma unroll
            for (int mt = 0; mt < 2; mt++) {
                int mr = wm * 32 + mt * 16;
                a[mt][0] = __float_as_uint(Xs[mr + gid][kk + tig]);
                a[mt][1] = __float_as_uint(Xs[mr + gid + 8][kk + tig]);
                a[mt][2] = __float_as_uint(Xs[mr + gid][kk + tig + 4]);
                a[mt][3] = __float_as_uint(Xs[mr + gid + 8][kk + tig + 4]);
            }
#pragma unroll
            for (int nt = 0; nt < 4; nt++) {
                int nr = wn * 32 + nt * 8;
                b[nt][0] = __float_as_uint(Ws[nr + gid][kk + tig]);
                b[nt][1] = __float_as_uint(Ws[nr + gid][kk + tig + 4]);
            }
#pragma unroll
            for (int mt = 0; mt < 2; mt++)
#pragma unroll
                for (int nt = 0; nt < 4; nt++) mma_tf32(acc[mt][nt], a[mt], b[nt]);
        }
        __syncthreads();
    }
#pragma unroll
    for (int mt = 0; mt < 2; mt++)
#pragma unroll
        for (int nt = 0; nt < 4; nt++) {
            int row = m0 + wm * 32 + mt * 16 + gid;
            int col = n0 + wn * 32 + nt * 8 + tig * 2;
            float bx = bias[col], by = bias[col + 1];
            float* p = out + (size_t)row * GG + col;
            p[0] = acc[mt][nt].x + bx;
            p[1] = acc[mt][nt].y + by;
            p += (size_t)8 * GG;
            p[0] = acc[mt][nt].z + bx;
            p[1] = acc[mt][nt].w + by;
        }
}

// ---------------------------------------------------------------------------
// Persistent recurrent scan, split-K edition.
// 128 blocks = 2 dirs x 64 j-tiles(8); 8 warps/block, warp w owns K-slice
// [w*64, w*64+64). W_hh fragments live in registers for the whole layer.
// Each warp: h slice (64b x 64k) via cp.async.cg -> private smem -> 128 mma.
// Cross-warp reduce of 8 partials + fused LSTM update. c in registers.
// smem: 8 warp regions of [64][68] floats (h slice, later aliased by partials)
// ---------------------------------------------------------------------------
#define REGW 4352            // 64*68 floats per warp region
#define SCAN_SMEM (8 * REGW * 4)

__global__ __launch_bounds__(256, 1)
void k_scan(const float* __restrict__ Whh0, const float* __restrict__ Whh1,
            int xoutsel) {
    extern __shared__ float s[];
    int bid = blockIdx.x;
    int dir = bid >> 6;
    int j0 = (bid & 63) * 8;
    const float* Whh = dir ? Whh1 : Whh0;
    const float* gx = g_gx[dir];
    float* xout = g_xbuf[xoutsel];

    int tid = threadIdx.x, lane = tid & 31, warp = tid >> 5;
    int gid = lane >> 2, tig = lane & 3;
    float* myH = s + warp * REGW;
    uint32_t myH_s;
    { void* p = myH; myH_s = (uint32_t)__cvta_generic_to_shared(p); }

    // W fragments: warp covers N=32 gate cols (4 ntiles x 8), K-slice = 64.
    // gate col c = nt*8+gid -> quadrant nt, row = nt*512 + j0 + gid.
    uint32_t wr[4][8][2];
#pragma unroll
    for (int nt = 0; nt < 4; nt++) {
        const float* wrow = Whh + (size_t)(nt * 512 + j0 + gid) * HH + warp * 64;
#pragma unroll
        for (int kk = 0; kk < 8; kk++) {
            wr[nt][kk][0] = __float_as_uint(to_tf32(__ldg(wrow + kk * 8 + tig)));
            wr[nt][kk][1] = __float_as_uint(to_tf32(__ldg(wrow + kk * 8 + tig + 4)));
        }
    }

    // fixed thread->cell map (2 cells: (b, j0+jj)); c state in registers
    int cb[2], cjj[2], clb[2], cbj[2];
    float creg[2], gxp[2][4];
#pragma unroll
    for (int it = 0; it < 2; it++) {
        int cell = it * 256 + tid;
        cb[it] = cell >> 3; cjj[it] = cell & 7;
        clb[it] = g_len[cb[it]];
        cbj[it] = cb[it] * HH + j0 + cjj[it];
        creg[it] = g_c[dir][cbj[it]];
    }

    // prefetch gx for step t
#define PREFETCH_GX(t)                                                        \
    {                                                                         \
        _Pragma("unroll")                                                     \
        for (int it = 0; it < 2; it++) {                                      \
            if ((t) < clb[it]) {                                              \
                int r = dir ? (clb[it] - 1 - (t)) * BB + cb[it]               \
                            : (t) * BB + cb[it];                              \
                const float* gp = gx + (size_t)r * GG + j0 + cjj[it];         \
                gxp[it][0] = __ldg(gp);                                       \
                gxp[it][1] = __ldg(gp + 512);                                 \
                gxp[it][2] = __ldg(gp + 1024);                                \
                gxp[it][3] = __ldg(gp + 1536);                                \
            }                                                                 \
        }                                                                     \
    }

    PREFETCH_GX(0)

    for (int t = 0; t < TT; t++) {
        const float* hcur = g_h[t & 1][dir];
        float* hnext = g_h[(t & 1) ^ 1][dir];

        // warp-private h slice: 64 rows x 64 cols at k0 = warp*64 (L2-scoped)
        const float* hsrc = hcur + warp * 64;
#pragma unroll
        for (int i = 0; i < 32; i++) {
            int idx = i * 32 + lane, r = idx >> 4, cq = idx & 15;
            cp_async16(myH_s + (uint32_t)(r * 68 + cq * 4) * 4,
                       hsrc + r * HH + cq * 4);
        }
        asm volatile("cp.async.commit_group;\n" ::: "memory");
        asm volatile("cp.async.wait_group 0;\n" ::: "memory");
        __syncwarp();

        float4 acc[4][4];
#pragma unroll
        for (int mt = 0; mt < 4; mt++)
#pragma unroll
            for (int nt = 0; nt < 4; nt++) acc[mt][nt] = make_float4(0.f, 0.f, 0.f, 0.f);

#pragma unroll
        for (int kk = 0; kk < 8; kk++) {
            uint32_t a[4][4];
            int c0 = kk * 8 + tig;
#pragma unroll
            for (int mt = 0; mt < 4; mt++) {
                int row = mt * 16 + gid;
                a[mt][0] = __float_as_uint(myH[row * 68 + c0]);
                a[mt][1] = __float_as_uint(myH[(row + 8) * 68 + c0]);
                a[mt][2] = __float_as_uint(myH[row * 68 + c0 + 4]);
                a[mt][3] = __float_as_uint(myH[(row + 8) * 68 + c0 + 4]);
            }
#pragma unroll
            for (int mt = 0; mt < 4; mt++)
#pragma unroll
                for (int nt = 0; nt < 4; nt++)
                    mma_tf32(acc[mt][nt], a[mt], wr[nt][kk]);
        }

        // partials aliased over own h region: P(b, col) at myH[b*68 + col]
        __syncwarp();
#pragma unroll
        for (int mt = 0; mt < 4; mt++)
#pragma unroll
            for (int nt = 0; nt < 4; nt++) {
                int row = mt * 16 + gid, col = nt * 8 + tig * 2;
                *(float2*)&myH[row * 68 + col] =
                    make_float2(acc[mt][nt].x, acc[mt][nt].y);
                *(float2*)&myH[(row + 8) * 68 + col] =
                    make_float2(acc[mt][nt].z, acc[mt][nt].w);
            }
        __syncthreads();

        // reduce 8 partials + fused LSTM update
#pragma unroll
        for (int it = 0; it < 2; it++) {
            int b = cb[it], jj = cjj[it], lb = clb[it], bj = cbj[it];
            float gsum[4] = {0.f, 0.f, 0.f, 0.f};
#pragma unroll
            for (int w = 0; w < 8; w++) {
                const float* pw = s + w * REGW + b * 68 + jj;
#pragma unroll
                for (int q = 0; q < 4; q++) gsum[q] += pw[q * 8];
            }
            if (t < lb) {
                float iv = gsum[0] + gxp[it][0];
                float fv = gsum[1] + gxp[it][1];
                float gv = gsum[2] + gxp[it][2];
                float ov = gsum[3] + gxp[it][3];
                float cn = sigm(fv) * creg[it] + sigm(iv) * tanhf(gv);
                float hn = sigm(ov) * tanhf(cn);
                creg[it] = cn;
                hnext[bj] = to_tf32(hn);
                int tout = dir ? (lb - 1 - t) : t;
                xout[(size_t)(tout * BB + b) * 1024 + dir * HH + j0 + jj] = hn;
            } else if (t < lb + 2) {
                hnext[bj] = __ldcg(hcur + bj);   // settle both ping-pong bufs
            }
        }

        PREFETCH_GX(t + 1)           // lands during the barrier wait

        __syncthreads();
        if (t < TT - 1) {
            if (tid == 0) {
                unsigned* bar = &g_bar2[dir][0];
                unsigned target = 64u * (unsigned)(t + 1);
                asm volatile("red.release.gpu.global.add.u32 [%0], %1;"
                             :: "l"(bar), "r"(1u) : "memory");
                unsigned v;
                do {
                    asm volatile("ld.acquire.gpu.global.u32 %0, [%1];"
                                 : "=r"(v) : "l"(bar) : "memory");
                } while (v < target);
            }
            __syncthreads();
        }
    }

#pragma unroll
    for (int it = 0; it < 2; it++) g_c[dir][cbj[it]] = creg[it];
#undef PREFETCH_GX
}

extern "C" void kernel_launch(void* const* d_in, const int* in_sizes, int n_in,
                              void* d_out, int out_size) {
    const float* data   = (const float*)d_in[0];
    const float* h0     = (const float*)d_in[1];
    const float* c0     = (const float*)d_in[2];
    const float* w_ih0  = (const float*)d_in[3];
    const float* w_hh0  = (const float*)d_in[4];
    const float* b0     = (const float*)d_in[5];
    const float* w_ih_r = (const float*)d_in[6];
    const float* w_hh_r = (const float*)d_in[7];
    const float* b_r    = (const float*)d_in[8];
    const int*   pack   = (const int*)d_in[10];

    const int NP = in_sizes[0] / 512;
    float* out = (float*)d_out;

    static int smem_set = 0;
    if (!smem_set) {
        cudaFuncSetAttribute(k_scan, cudaFuncAttributeMaxDynamicSharedMemorySize,
                             SCAN_SMEM);
        smem_set = 1;
    }

    k_len<<<1, 1024>>>(pack, NP);
    k_scatter<<<(NP * 512 + 255) / 256, 256>>>(data, pack, NP * 512);

    const int LX[3]  = {0, 1, 0};
    const int LLD[3] = {512, 1024, 1024};
    const int LK[3]  = {512, 1024, 1024};
    const int LO[3]  = {1, 0, 1};

    for (int l = 0; l < 3; l++) {
        for (int d = 0; d < 2; d++) {
            const float* Wih = (l == 0)
                ? w_ih0 + (size_t)d * GG * 512
                : w_ih_r + (size_t)((l - 1) * 2 + d) * GG * 1024;
            const float* bs = (l == 0)
                ? b0 + (size_t)d * GG
                : b_r + (size_t)((l - 1) * 2 + d) * GG;
            k_gemm_gx<<<dim3(TB / 128, GG / 64), 256>>>(LX[l], LLD[l], LK[l], Wih, bs, d);
        }
        k_init<<<256, 256>>>(h0, c0, l);

        const float* W0 = (l == 0) ? w_hh0
                                   : w_hh_r + (size_t)((l - 1) * 2 + 0) * GG * HH;
        const float* W1 = (l == 0) ? w_hh0 + (size_t)GG * HH
                                   : w_hh_r + (size_t)((l - 1) * 2 + 1) * GG * HH;
        k_scan<<<128, 256, SCAN_SMEM>>>(W0, W1, LO[l]);

        k_save<<<256, 256>>>(out, NP, l);
    }
    k_gather<<<(NP * 1024 + 255) / 256, 256>>>(out, pack, NP * 1024);
}

// round 13
// speedup vs baseline: 1.5162x; 1.2225x over previous
#include <cuda_runtime.h>
#include <cuda_fp16.h>
#include <cstdint>

#define TT 512
#define BB 64
#define HH 512
#define GG 2048
#define TB (TT*BB)

__device__ __align__(16) float  g_xbuf[2][(size_t)TB * 1024];
__device__ __align__(16) float  g_gx[2][(size_t)TB * GG];
__device__ __align__(16) __half g_h16[2][2][BB * HH];   // [parity][dir], mma feed
__device__ __align__(16) float  g_hout[2][BB * HH];     // full-precision h_n
__device__ __align__(16) float  g_c[2][BB * HH];
__device__ int g_len[BB];
__device__ unsigned g_bar2[2][32];

__device__ __forceinline__ float sigm(float x) { return 1.0f / (1.0f + expf(-x)); }

__device__ __forceinline__ void cp_async16(uint32_t saddr, const void* gaddr) {
    asm volatile("cp.async.cg.shared.global [%0], [%1], 16;\n"
                 :: "r"(saddr), "l"(gaddr));
}
__device__ __forceinline__ void ldsm_x4(uint32_t& r0, uint32_t& r1,
                                        uint32_t& r2, uint32_t& r3, uint32_t saddr) {
    asm volatile("ldmatrix.sync.aligned.m8n8.x4.shared.b16 {%0,%1,%2,%3}, [%4];"
                 : "=r"(r0), "=r"(r1), "=r"(r2), "=r"(r3) : "r"(saddr));
}
__device__ __forceinline__ void mma_f16(float4& d, const uint32_t* a, const uint32_t* b) {
    asm volatile(
        "mma.sync.aligned.m16n8k16.row.col.f32.f16.f16.f32 "
        "{%0,%1,%2,%3}, {%4,%5,%6,%7}, {%8,%9}, {%0,%1,%2,%3};\n"
        : "+f"(d.x), "+f"(d.y), "+f"(d.z), "+f"(d.w)
        : "r"(a[0]), "r"(a[1]), "r"(a[2]), "r"(a[3]), "r"(b[0]), "r"(b[1]));
}
__device__ __forceinline__ uint32_t h2u(__half2 h) {
    return *reinterpret_cast<uint32_t*>(&h);
}

__global__ void k_len(const int* __restrict__ pack_idx, int NP) {
    __shared__ int cnt[BB];
    int tid = threadIdx.x;
    if (tid < BB) cnt[tid] = 0;
    __syncthreads();
    for (int i = tid; i < NP; i += blockDim.x)
        atomicAdd(&cnt[pack_idx[i] & (BB - 1)], 1);
    __syncthreads();
    if (tid < BB) g_len[tid] = cnt[tid];
}

__global__ void k_scatter(const float* __restrict__ data, const int* __restrict__ pack_idx, int total) {
    int e = blockIdx.x * blockDim.x + threadIdx.x;
    if (e < total) {
        int i = e >> 9, col = e & 511;
        g_xbuf[0][(size_t)pack_idx[i] * 512 + col] = data[e];
    }
}

__global__ void k_gather(float* __restrict__ out, const int* __restrict__ pack_idx, int total) {
    int e = blockIdx.x * blockDim.x + threadIdx.x;
    if (e < total) {
        int i = e >> 10, col = e & 1023;
        out[e] = g_xbuf[1][(size_t)pack_idx[i] * 1024 + col];
    }
}

__global__ void k_init(const float* __restrict__ h0, const float* __restrict__ c0, int l) {
    int idx = blockIdx.x * blockDim.x + threadIdx.x;
    if (idx < 2) g_bar2[idx][0] = 0u;
    int dir = idx >> 15, rem = idx & 32767;
    size_t src = (size_t)(2 * l + dir) * 32768 + rem;
    float h = h0[src];
    g_h16[0][dir][rem] = __float2half_rn(h);
    g_hout[dir][rem]   = h;
    g_c[dir][rem]      = c0[src];
}

__global__ void k_save(float* __restrict__ out, int NP, int l) {
    int idx = blockIdx.x * blockDim.x + threadIdx.x;
    int dir = idx >> 15, rem = idx & 32767;
    size_t OH = (size_t)NP * 1024;
    size_t off = (size_t)(2 * l + dir) * 32768 + rem;
    out[OH + off]             = g_hout[dir][rem];
    out[OH + 6 * 32768 + off] = g_c[dir][rem];
}

// ---------------------------------------------------------------------------
// Input GEMM, fp16 edition: gx[m,n] = bias[n] + sum_k X[m,k]*W[n,k]
// 128x64x32 tiles; fp16 smem (padded pitch 40 halves), ldmatrix fragments,
// m16n8k16 f16 mma with f32 accumulate. 8 warps (4m x 2n).
// ---------------------------------------------------------------------------
__global__ __launch_bounds__(256)
void k_gemm_gx(int xsel, int ldx, int K, const float* __restrict__ W,
               const float* __restrict__ bias, int dir) {
    const float* X = g_xbuf[xsel];
    float* out = g_gx[dir];
    __shared__ __half Xs[128 * 40];
    __shared__ __half Ws[64 * 40];
    uint32_t Xs_s = (uint32_t)__cvta_generic_to_shared(Xs);
    uint32_t Ws_s = (uint32_t)__cvta_generic_to_shared(Ws);

    int tid = threadIdx.x, lane = tid & 31, warp = tid >> 5;
    int wm = warp & 3, wn = warp >> 2;
    int gid = lane >> 2, tig = lane & 3;
    int sel = lane >> 3, rowin = lane & 7;
    int m0 = blockIdx.x * 128, n0 = blockIdx.y * 64;

    float4 acc[2][4];
#pragma unroll
    for (int mt = 0; mt < 2; mt++)
#pragma unroll
        for (int nt = 0; nt < 4; nt++) acc[mt][nt] = make_float4(0.f, 0.f, 0.f, 0.f);

    for (int k0 = 0; k0 < K; k0 += 32) {
#pragma unroll
        for (int it = 0; it < 4; it++) {
            int idx = it * 256 + tid, r = idx >> 3, kq = idx & 7;
            float4 v = *(const float4*)(X + (size_t)(m0 + r) * ldx + k0 + kq * 4);
            uint2 h = { h2u(__floats2half2_rn(v.x, v.y)),
                        h2u(__floats2half2_rn(v.z, v.w)) };
            *(uint2*)(Xs + r * 40 + kq * 4) = h;
        }
#pragma unroll
        for (int it = 0; it < 2; it++) {
            int idx = it * 256 + tid, r = idx >> 3, kq = idx & 7;
            float4 v = *(const float4*)(W + (size_t)(n0 + r) * K + k0 + kq * 4);
            uint2 h = { h2u(__floats2half2_rn(v.x, v.y)),
                        h2u(__floats2half2_rn(v.z, v.w)) };
            *(uint2*)(Ws + r * 40 + kq * 4) = h;
        }
        __syncthreads();
#pragma unroll
        for (int kk = 0; kk < 2; kk++) {
            uint32_t a[2][4], b[4][2];
#pragma unroll
            for (int mt = 0; mt < 2; mt++) {
                int m = wm * 32 + mt * 16 + (sel & 1) * 8 + rowin;
                int c8 = kk * 2 + (sel >> 1);
                ldsm_x4(a[mt][0], a[mt][1], a[mt][2], a[mt][3],
                        Xs_s + (uint32_t)(m * 80 + c8 * 16));
            }
#pragma unroll
            for (int p = 0; p < 2; p++) {
                int quad = lane >> 3;
                int n = wn * 32 + p * 16 + (quad >> 1) * 8 + rowin;
                int c8 = kk * 2 + (quad & 1);
                ldsm_x4(b[p * 2][0], b[p * 2][1], b[p * 2 + 1][0], b[p * 2 + 1][1],
                        Ws_s + (uint32_t)(n * 80 + c8 * 16));
            }
#pragma unroll
            for (int mt = 0; mt < 2; mt++)
#pragma unroll
                for (int nt = 0; nt < 4; nt++) mma_f16(acc[mt][nt], a[mt], b[nt]);
        }
        __syncthreads();
    }
#pragma unroll
    for (int mt = 0; mt < 2; mt++)
#pragma unroll
        for (int nt = 0; nt < 4; nt++) {
            int row = m0 + wm * 32 + mt * 16 + gid;
            int col = n0 + wn * 32 + nt * 8 + tig * 2;
            float bx = bias[col], by = bias[col + 1];
            float* p = out + (size_t)row * GG + col;
            p[0] = acc[mt][nt].x + bx;
            p[1] = acc[mt][nt].y + by;
            p += (size_t)8 * GG;
            p[0] = acc[mt][nt].z + bx;
            p[1] = acc[mt][nt].w + by;
        }
}

// ---------------------------------------------------------------------------
// Persistent scan, fp16 split-K. 128 blocks = 2 dirs x 64 j-tiles(8);
// warp w owns K-slice [w*64, w*64+64). W in registers (fp16), h in fp16
// via cp.async into XOR-swizzled smem, a-frags via ldmatrix.x4.
// Region per warp: 64 rows; h16 at pitch 128B (swizzled), partials f32
// at pitch 40 words (aliased after mma).
// ---------------------------------------------------------------------------
#define REGF 2560                 // floats per warp region (64 * 40)
#define SCAN_SMEM (8 * REGF * 4)  // 80 KB

__global__ __launch_bounds__(256, 1)
void k_scan(const float* __restrict__ Whh0, const float* __restrict__ Whh1,
            int xoutsel) {
    extern __shared__ float s[];
    int bid = blockIdx.x;
    int dir = bid >> 6;
    int j0 = (bid & 63) * 8;
    const float* Whh = dir ? Whh1 : Whh0;
    const float* gx = g_gx[dir];
    float* xout = g_xbuf[xoutsel];

    int tid = threadIdx.x, lane = tid & 31, warp = tid >> 5;
    int gid = lane >> 2, tig = lane & 3;
    int sel = lane >> 3, rowin = lane & 7;
    float* myR = s + warp * REGF;
    uint32_t myR_s = (uint32_t)__cvta_generic_to_shared(myR);

    // precomputed ldmatrix lane address pieces
    int hi = sel >> 1;
    uint32_t mbase[4];
    int m7[4];
#pragma unroll
    for (int mt = 0; mt < 4; mt++) {
        int m = mt * 16 + (sel & 1) * 8 + rowin;
        mbase[mt] = myR_s + (uint32_t)(m * 128);
        m7[mt] = m & 7;
    }

    // W fragments (fp16): 4 ntiles x 4 k16-steps x 2 regs
    uint32_t wr[4][4][2];
#pragma unroll
    for (int nt = 0; nt < 4; nt++) {
        const float* wrow = Whh + (size_t)(nt * 512 + j0 + gid) * HH + warp * 64;
#pragma unroll
        for (int kk = 0; kk < 4; kk++) {
            const float* wp = wrow + kk * 16;
            wr[nt][kk][0] = h2u(__floats2half2_rn(__ldg(wp + 2 * tig),
                                                  __ldg(wp + 2 * tig + 1)));
            wr[nt][kk][1] = h2u(__floats2half2_rn(__ldg(wp + 2 * tig + 8),
                                                  __ldg(wp + 2 * tig + 9)));
        }
    }

    // fixed thread->cell map (2 cells); c in registers
    int cb[2], cjj[2], clb[2], cbj[2];
    float creg[2], gxp[2][4];
#pragma unroll
    for (int it = 0; it < 2; it++) {
        int cell = it * 256 + tid;
        cb[it] = cell >> 3; cjj[it] = cell & 7;
        clb[it] = g_len[cb[it]];
        cbj[it] = cb[it] * HH + j0 + cjj[it];
        creg[it] = g_c[dir][cbj[it]];
    }

#define PREFETCH_GX(t)                                                        \
    {                                                                         \
        _Pragma("unroll")                                                     \
        for (int it = 0; it < 2; it++) {                                      \
            if ((t) < clb[it]) {                                              \
                int r = dir ? (clb[it] - 1 - (t)) * BB + cb[it]               \
                            : (t) * BB + cb[it];                              \
                const float* gp = gx + (size_t)r * GG + j0 + cjj[it];         \
                gxp[it][0] = __ldg(gp);                                       \
                gxp[it][1] = __ldg(gp + 512);                                 \
                gxp[it][2] = __ldg(gp + 1024);                                \
                gxp[it][3] = __ldg(gp + 1536);                                \
            }                                                                 \
        }                                                                     \
    }

    PREFETCH_GX(0)

    for (int t = 0; t < TT; t++) {
        const __half* hcur16 = g_h16[t & 1][dir];
        __half* hnext16 = g_h16[(t & 1) ^ 1][dir];
        const __half* hsrc = hcur16 + warp * 64;

        // h slice 64 rows x 64 halves, XOR-swizzled 128B pitch, 2 groups
#pragma unroll
        for (int g = 0; g < 2; g++) {
#pragma unroll
            for (int i = 0; i < 8; i++) {
                int idx = (g * 8 + i) * 32 + lane;
                int r = idx & 63, c8 = idx >> 6;
                uint32_t byteoff = (uint32_t)(r * 128 + ((c8 ^ (r & 7)) << 4));
                cp_async16(myR_s + byteoff, hsrc + (size_t)r * HH + c8 * 8);
            }
            asm volatile("cp.async.commit_group;\n" ::: "memory");
        }

        float4 acc[4][4];
#pragma unroll
        for (int mt = 0; mt < 4; mt++)
#pragma unroll
            for (int nt = 0; nt < 4; nt++) acc[mt][nt] = make_float4(0.f, 0.f, 0.f, 0.f);

        asm volatile("cp.async.wait_group 1;\n" ::: "memory");
        __syncwarp();
#pragma unroll
        for (int kk = 0; kk < 2; kk++) {
            uint32_t a[4];
#pragma unroll
            for (int mt = 0; mt < 4; mt++) {
                ldsm_x4(a[0], a[1], a[2], a[3],
                        mbase[mt] + (uint32_t)((((kk * 2 + hi) ^ m7[mt]) << 4)));
#pragma unroll
                for (int nt = 0; nt < 4; nt++) mma_f16(acc[mt][nt], a, wr[nt][kk]);
            }
        }
        asm volatile("cp.async.wait_group 0;\n" ::: "memory");
        __syncwarp();
#pragma unroll
        for (int kk = 2; kk < 4; kk++) {
            uint32_t a[4];
#pragma unroll
            for (int mt = 0; mt < 4; mt++) {
                ldsm_x4(a[0], a[1], a[2], a[3],
                        mbase[mt] + (uint32_t)((((kk * 2 + hi) ^ m7[mt]) << 4)));
#pragma unroll
                for (int nt = 0; nt < 4; nt++) mma_f16(acc[mt][nt], a, wr[nt][kk]);
            }
        }
        __syncwarp();

        // partials (f32, pitch 40) aliased over own region
#pragma unroll
        for (int mt = 0; mt < 4; mt++)
#pragma unroll
            for (int nt = 0; nt < 4; nt++) {
                int row = mt * 16 + gid, col = nt * 8 + tig * 2;
                *(float2*)&myR[row * 40 + col] =
                    make_float2(acc[mt][nt].x, acc[mt][nt].y);
                *(float2*)&myR[(row + 8) * 40 + col] =
                    make_float2(acc[mt][nt].z, acc[mt][nt].w);
            }
        __syncthreads();

        // reduce 8 partials + fused LSTM update
#pragma unroll
        for (int it = 0; it < 2; it++) {
            int b = cb[it], jj = cjj[it], lb = clb[it], bj = cbj[it];
            float gsum[4] = {0.f, 0.f, 0.f, 0.f};
#pragma unroll
            for (int w = 0; w < 8; w++) {
                const float* pw = s + w * REGF + b * 40 + jj;
#pragma unroll
                for (int q = 0; q < 4; q++) gsum[q] += pw[q * 8];
            }
            if (t < lb) {
                float iv = gsum[0] + gxp[it][0];
                float fv = gsum[1] + gxp[it][1];
                float gv = gsum[2] + gxp[it][2];
                float ov = gsum[3] + gxp[it][3];
                float cn = sigm(fv) * creg[it] + sigm(iv) * tanhf(gv);
                float hn = sigm(ov) * tanhf(cn);
                creg[it] = cn;
                hnext16[bj] = __float2half_rn(hn);
                if (t == lb - 1) g_hout[dir][bj] = hn;
                int tout = dir ? (lb - 1 - t) : t;
                xout[(size_t)(tout * BB + b) * 1024 + dir * HH + j0 + jj] = hn;
            } else if (t < lb + 2) {
                hnext16[bj] = hcur16[bj];   // settle both parity buffers
            }
        }

        PREFETCH_GX(t + 1)

        __syncthreads();
        if (t < TT - 1) {
            if (tid == 0) {
                unsigned* bar = &g_bar2[dir][0];
                unsigned target = 64u * (unsigned)(t + 1);
                asm volatile("red.release.gpu.global.add.u32 [%0], %1;"
                             :: "l"(bar), "r"(1u) : "memory");
                unsigned v;
                do {
                    asm volatile("ld.acquire.gpu.global.u32 %0, [%1];"
                                 : "=r"(v) : "l"(bar) : "memory");
                } while (v < target);
            }
            __syncthreads();
        }
    }

#pragma unroll
    for (int it = 0; it < 2; it++) g_c[dir][cbj[it]] = creg[it];
#undef PREFETCH_GX
}

extern "C" void kernel_launch(void* const* d_in, const int* in_sizes, int n_in,
                              void* d_out, int out_size) {
    const float* data   = (const float*)d_in[0];
    const float* h0     = (const float*)d_in[1];
    const float* c0     = (const float*)d_in[2];
    const float* w_ih0  = (const float*)d_in[3];
    const float* w_hh0  = (const float*)d_in[4];
    const float* b0     = (const float*)d_in[5];
    const float* w_ih_r = (const float*)d_in[6];
    const float* w_hh_r = (const float*)d_in[7];
    const float* b_r    = (const float*)d_in[8];
    const int*   pack   = (const int*)d_in[10];

    const int NP = in_sizes[0] / 512;
    float* out = (float*)d_out;

    static int smem_set = 0;
    if (!smem_set) {
        cudaFuncSetAttribute(k_scan, cudaFuncAttributeMaxDynamicSharedMemorySize,
                             SCAN_SMEM);
        smem_set = 1;
    }

    k_len<<<1, 1024>>>(pack, NP);
    k_scatter<<<(NP * 512 + 255) / 256, 256>>>(data, pack, NP * 512);

    const int LX[3]  = {0, 1, 0};
    const int LLD[3] = {512, 1024, 1024};
    const int LK[3]  = {512, 1024, 1024};
    const int LO[3]  = {1, 0, 1};

    for (int l = 0; l < 3; l++) {
        for (int d = 0; d < 2; d++) {
            const float* Wih = (l == 0)
                ? w_ih0 + (size_t)d * GG * 512
                : w_ih_r + (size_t)((l - 1) * 2 + d) * GG * 1024;
            const float* bs = (l == 0)
                ? b0 + (size_t)d * GG
                : b_r + (size_t)((l - 1) * 2 + d) * GG;
            k_gemm_gx<<<dim3(TB / 128, GG / 64), 256>>>(LX[l], LLD[l], LK[l], Wih, bs, d);
        }
        k_init<<<256, 256>>>(h0, c0, l);

        const float* W0 = (l == 0) ? w_hh0
                                   : w_hh_r + (size_t)((l - 1) * 2 + 0) * GG * HH;
        const float* W1 = (l == 0) ? w_hh0 + (size_t)GG * HH
                                   : w_hh_r + (size_t)((l - 1) * 2 + 1) * GG * HH;
        k_scan<<<128, 256, SCAN_SMEM>>>(W0, W1, LO[l]);

        k_save<<<256, 256>>>(out, NP, l);
    }
    k_gather<<<(NP * 1024 + 255) / 256, 256>>>(out, pack, NP * 1024);
}

// round 14
// speedup vs baseline: 1.7751x; 1.1707x over previous
#include <cuda_runtime.h>
#include <cuda_fp16.h>
#include <cstdint>

#define TT 512
#define BB 64
#define HH 512
#define GG 2048
#define TB (TT*BB)

__device__ __align__(16) __half g_x16[2][(size_t)TB * 1024];   // layer activations (fp16)
__device__ __align__(16) float  g_xf[(size_t)TB * 1024];       // final-layer fp32 output
__device__ __align__(16) __half g_gx16[2][(size_t)TB * 2048];  // gate-interleaved [r][j][4]
__device__ __align__(16) __half g_w16[2 * 2048 * 1024];        // per-layer W_ih fp16
__device__ __align__(16) __half g_h16[2][2][BB * HH];
__device__ __align__(16) float  g_hout[2][BB * HH];
__device__ __align__(16) float  g_c[2][BB * HH];
__device__ int g_len[BB];
__device__ int g_nact[TT];
__device__ unsigned g_bar2[2][32];

__device__ __forceinline__ float sigm(float x) { return 1.0f / (1.0f + expf(-x)); }
__device__ __forceinline__ void cp_async16(uint32_t saddr, const void* gaddr) {
    asm volatile("cp.async.cg.shared.global [%0], [%1], 16;\n" :: "r"(saddr), "l"(gaddr));
}
__device__ __forceinline__ void ldsm_x4(uint32_t& r0, uint32_t& r1,
                                        uint32_t& r2, uint32_t& r3, uint32_t saddr) {
    asm volatile("ldmatrix.sync.aligned.m8n8.x4.shared.b16 {%0,%1,%2,%3}, [%4];"
                 : "=r"(r0), "=r"(r1), "=r"(r2), "=r"(r3) : "r"(saddr));
}
__device__ __forceinline__ void mma_f16(float4& d, const uint32_t* a, const uint32_t* b) {
    asm volatile(
        "mma.sync.aligned.m16n8k16.row.col.f32.f16.f16.f32 "
        "{%0,%1,%2,%3}, {%4,%5,%6,%7}, {%8,%9}, {%0,%1,%2,%3};\n"
        : "+f"(d.x), "+f"(d.y), "+f"(d.z), "+f"(d.w)
        : "r"(a[0]), "r"(a[1]), "r"(a[2]), "r"(a[3]), "r"(b[0]), "r"(b[1]));
}
__device__ __forceinline__ uint32_t h2u(__half2 h) { return *reinterpret_cast<uint32_t*>(&h); }

__global__ void k_len(const int* __restrict__ pack_idx, int NP) {
    __shared__ int cnt[BB];
    int tid = threadIdx.x;
    if (tid < BB) cnt[tid] = 0;
    __syncthreads();
    for (int i = tid; i < NP; i += blockDim.x)
        atomicAdd(&cnt[pack_idx[i] & (BB - 1)], 1);
    __syncthreads();
    if (tid < BB) g_len[tid] = cnt[tid];
    if (tid < TT) {
        int t = tid, na = 0;
#pragma unroll 8
        for (int b = 0; b < BB; b++) na += (cnt[b] > t) ? 1 : 0;
        g_nact[t] = na;
    }
}

__global__ void k_wcvt(const float* __restrict__ W, int n4) {
    int i = blockIdx.x * blockDim.x + threadIdx.x;
    if (i < n4) {
        float4 v = *(const float4*)(W + (size_t)i * 4);
        uint2 h = { h2u(__floats2half2_rn(v.x, v.y)), h2u(__floats2half2_rn(v.z, v.w)) };
        *(uint2*)(g_w16 + (size_t)i * 4) = h;
    }
}

__global__ void k_scatter(const float* __restrict__ data, const int* __restrict__ pack_idx, int total) {
    int e = blockIdx.x * blockDim.x + threadIdx.x;
    if (e < total) {
        int i = e >> 9, col = e & 511;
        g_x16[0][(size_t)pack_idx[i] * 512 + col] = __float2half_rn(data[e]);
    }
}

__global__ void k_gather(float* __restrict__ out, const int* __restrict__ pack_idx, int total) {
    int e = blockIdx.x * blockDim.x + threadIdx.x;
    if (e < total) {
        int i = e >> 10, col = e & 1023;
        out[e] = g_xf[(size_t)pack_idx[i] * 1024 + col];
    }
}

__global__ void k_init(const float* __restrict__ h0, const float* __restrict__ c0, int l) {
    int idx = blockIdx.x * blockDim.x + threadIdx.x;
    if (idx < 2) g_bar2[idx][0] = 0u;
    int dir = idx >> 15, rem = idx & 32767;
    size_t src = (size_t)(2 * l + dir) * 32768 + rem;
    float h = h0[src];
    g_h16[0][dir][rem] = __float2half_rn(h);
    g_hout[dir][rem]   = h;
    g_c[dir][rem]      = c0[src];
}

__global__ void k_save(float* __restrict__ out, int NP, int l) {
    int idx = blockIdx.x * blockDim.x + threadIdx.x;
    int dir = idx >> 15, rem = idx & 32767;
    size_t OH = (size_t)NP * 1024;
    size_t off = (size_t)(2 * l + dir) * 32768 + rem;
    out[OH + off]             = g_hout[dir][rem];
    out[OH + 6 * 32768 + off] = g_c[dir][rem];
}

// ---------------------------------------------------------------------------
// Input GEMM, cp.async 3-stage pipeline, all-fp16 operands.
// grid = (32 n-tiles, 256 m-tiles)  [n fast -> X reused 32x from L2]
// Writes gx gate-interleaved fp16: g_gx16[dir][row*2048 + j*4 + quad].
// ---------------------------------------------------------------------------
__global__ __launch_bounds__(256)
void k_gemm_gx(int xsel, int ldx, int K, int dir, const float* __restrict__ bias) {
    const __half* X = g_x16[xsel];
    const __half* W = g_w16 + (size_t)dir * 2048 * K;
    __half* og = g_gx16[dir];

    __shared__ __align__(16) __half Xs[3][128 * 40];
    __shared__ __align__(16) __half Wsm[3][64 * 40];
    uint32_t Xs_s = (uint32_t)__cvta_generic_to_shared(&Xs[0][0]);
    uint32_t Ws_s = (uint32_t)__cvta_generic_to_shared(&Wsm[0][0]);

    int tid = threadIdx.x, lane = tid & 31, warp = tid >> 5;
    int wm = warp & 3, wn = warp >> 2;
    int gid = lane >> 2, tig = lane & 3;
    int sel = lane >> 3, rowin = lane & 7;
    int n0 = blockIdx.x * 64, m0 = blockIdx.y * 128;
    int NC = K / 32;

    float4 acc[2][4];
#pragma unroll
    for (int mt = 0; mt < 2; mt++)
#pragma unroll
        for (int nt = 0; nt < 4; nt++) acc[mt][nt] = make_float4(0.f, 0.f, 0.f, 0.f);

#define GPREF(kc, st)                                                          \
    {                                                                          \
        int k0 = (kc) * 32;                                                    \
        uint32_t xb = Xs_s + (uint32_t)(st) * 10240;                           \
        _Pragma("unroll")                                                      \
        for (int i = 0; i < 2; i++) {                                          \
            int idx = i * 256 + tid, r = idx >> 2, c = idx & 3;                \
            cp_async16(xb + (uint32_t)(r * 80 + c * 16),                       \
                       X + (size_t)(m0 + r) * ldx + k0 + c * 8);               \
        }                                                                      \
        uint32_t wb = Ws_s + (uint32_t)(st) * 5120;                            \
        { int r = tid >> 2, c = tid & 3;                                       \
          cp_async16(wb + (uint32_t)(r * 80 + c * 16),                         \
                     W + (size_t)(n0 + r) * K + k0 + c * 8); }                 \
        asm volatile("cp.async.commit_group;\n" ::: "memory");                 \
    }

    GPREF(0, 0)
    GPREF(1, 1)

    for (int kc = 0; kc < NC; kc++) {
        asm volatile("cp.async.wait_group 1;\n" ::: "memory");
        __syncthreads();
        if (kc + 2 < NC) GPREF(kc + 2, (kc + 2) % 3)
        uint32_t xb = Xs_s + (uint32_t)(kc % 3) * 10240;
        uint32_t wb = Ws_s + (uint32_t)(kc % 3) * 5120;
#pragma unroll
        for (int kk = 0; kk < 2; kk++) {
            uint32_t a[2][4], b[4][2];
#pragma unroll
            for (int mt = 0; mt < 2; mt++) {
                int m = wm * 32 + mt * 16 + (sel & 1) * 8 + rowin;
                int c8 = kk * 2 + (sel >> 1);
                ldsm_x4(a[mt][0], a[mt][1], a[mt][2], a[mt][3],
                        xb + (uint32_t)(m * 80 + c8 * 16));
            }
#pragma unroll
            for (int p = 0; p < 2; p++) {
                int quad = lane >> 3;
                int n = wn * 32 + p * 16 + (quad >> 1) * 8 + rowin;
                int c8 = kk * 2 + (quad & 1);
                ldsm_x4(b[p * 2][0], b[p * 2][1], b[p * 2 + 1][0], b[p * 2 + 1][1],
                        wb + (uint32_t)(n * 80 + c8 * 16));
            }
#pragma unroll
            for (int mt = 0; mt < 2; mt++)
#pragma unroll
                for (int nt = 0; nt < 4; nt++) mma_f16(acc[mt][nt], a[mt], b[nt]);
        }
    }
#undef GPREF

#pragma unroll
    for (int mt = 0; mt < 2; mt++)
#pragma unroll
        for (int nt = 0; nt < 4; nt++) {
            int row = m0 + wm * 32 + mt * 16 + gid;
            int col = n0 + wn * 32 + nt * 8 + tig * 2;
            int quad = col >> 9, j = col & 511;
            float bx = bias[col], by = bias[col + 1];
            size_t base = (size_t)row * 2048 + j * 4 + quad;
            og[base]     = __float2half_rn(acc[mt][nt].x + bx);
            og[base + 4] = __float2half_rn(acc[mt][nt].y + by);
            base += (size_t)8 * 2048;
            og[base]     = __float2half_rn(acc[mt][nt].z + bx);
            og[base + 4] = __float2half_rn(acc[mt][nt].w + by);
        }
}

// ---------------------------------------------------------------------------
// Persistent scan (fp16 split-K). Changes vs R13: gx16 interleaved prefetch
// moved AFTER barrier arrive; active-tile bounding via g_nact.
// ---------------------------------------------------------------------------
#define REGF 2560
#define SCAN_SMEM (8 * REGF * 4)

__global__ __launch_bounds__(256, 1)
void k_scan(const float* __restrict__ Whh0, const float* __restrict__ Whh1,
            int xoutsel, int final) {
    extern __shared__ float s[];
    int bid = blockIdx.x;
    int dir = bid >> 6;
    int j0 = (bid & 63) * 8;
    const float* Whh = dir ? Whh1 : Whh0;
    const __half* gx = g_gx16[dir];
    __half* xo16 = g_x16[xoutsel];

    int tid = threadIdx.x, lane = tid & 31, warp = tid >> 5;
    int gid = lane >> 2, tig = lane & 3;
    int sel = lane >> 3, rowin = lane & 7;
    float* myR = s + warp * REGF;
    uint32_t myR_s = (uint32_t)__cvta_generic_to_shared(myR);

    int hi = sel >> 1;
    uint32_t mbase[4];
    int m7[4];
#pragma unroll
    for (int mt = 0; mt < 4; mt++) {
        int m = mt * 16 + (sel & 1) * 8 + rowin;
        mbase[mt] = myR_s + (uint32_t)(m * 128);
        m7[mt] = m & 7;
    }

    uint32_t wr[4][4][2];
#pragma unroll
    for (int nt = 0; nt < 4; nt++) {
        const float* wrow = Whh + (size_t)(nt * 512 + j0 + gid) * HH + warp * 64;
#pragma unroll
        for (int kk = 0; kk < 4; kk++) {
            const float* wp = wrow + kk * 16;
            wr[nt][kk][0] = h2u(__floats2half2_rn(__ldg(wp + 2 * tig), __ldg(wp + 2 * tig + 1)));
            wr[nt][kk][1] = h2u(__floats2half2_rn(__ldg(wp + 2 * tig + 8), __ldg(wp + 2 * tig + 9)));
        }
    }

    int cb[2], cjj[2], clb[2], cbj[2];
    float creg[2];
    uint2 gxp[2];
#pragma unroll
    for (int it = 0; it < 2; it++) {
        int cell = it * 256 + tid;
        cb[it] = cell >> 3; cjj[it] = cell & 7;
        clb[it] = g_len[cb[it]];
        cbj[it] = cb[it] * HH + j0 + cjj[it];
        creg[it] = g_c[dir][cbj[it]];
    }

#define PREFETCH_GX(t)                                                        \
    {                                                                         \
        _Pragma("unroll")                                                     \
        for (int it = 0; it < 2; it++) {                                      \
            if ((t) < clb[it]) {                                              \
                int r = dir ? (clb[it] - 1 - (t)) * BB + cb[it]               \
                            : (t) * BB + cb[it];                             \
                gxp[it] = *(const uint2*)(gx + (size_t)r * 2048               \
                                              + (j0 + cjj[it]) * 4);          \
            }                                                                 \
        }                                                                     \
    }

    int na = g_nact[0];
    PREFETCH_GX(0)

    for (int t = 0; t < TT; t++) {
        const __half* hcur16 = g_h16[t & 1][dir];
        __half* hnext16 = g_h16[(t & 1) ^ 1][dir];
        const __half* hsrc = hcur16 + warp * 64;
        int mtmax = (na + 15) >> 4;
        bool upper = na > 32;

#pragma unroll
        for (int g = 0; g < 2; g++) {
#pragma unroll
            for (int i = 0; i < 8; i++) {
                if ((i & 1) && !upper) continue;    // rows 32..63 inactive
                int idx = (g * 8 + i) * 32 + lane;
                int r = idx & 63, c8 = idx >> 6;
                uint32_t byteoff = (uint32_t)(r * 128 + ((c8 ^ (r & 7)) << 4));
                cp_async16(myR_s + byteoff, hsrc + (size_t)r * HH + c8 * 8);
            }
            asm volatile("cp.async.commit_group;\n" ::: "memory");
        }

        float4 acc[4][4];
#pragma unroll
        for (int mt = 0; mt < 4; mt++)
#pragma unroll
            for (int nt = 0; nt < 4; nt++) acc[mt][nt] = make_float4(0.f, 0.f, 0.f, 0.f);

        asm volatile("cp.async.wait_group 1;\n" ::: "memory");
        __syncwarp();
#pragma unroll
        for (int kk = 0; kk < 2; kk++) {
            uint32_t a[4];
#pragma unroll
            for (int mt = 0; mt < 4; mt++) {
                if (mt >= mtmax) break;
                ldsm_x4(a[0], a[1], a[2], a[3],
                        mbase[mt] + (uint32_t)((((kk * 2 + hi) ^ m7[mt]) << 4)));
#pragma unroll
                for (int nt = 0; nt < 4; nt++) mma_f16(acc[mt][nt], a, wr[nt][kk]);
            }
        }
        asm volatile("cp.async.wait_group 0;\n" ::: "memory");
        __syncwarp();
#pragma unroll
        for (int kk = 2; kk < 4; kk++) {
            uint32_t a[4];
#pragma unroll
            for (int mt = 0; mt < 4; mt++) {
                if (mt >= mtmax) break;
                ldsm_x4(a[0], a[1], a[2], a[3],
                        mbase[mt] + (uint32_t)((((kk * 2 + hi) ^ m7[mt]) << 4)));
#pragma unroll
                for (int nt = 0; nt < 4; nt++) mma_f16(acc[mt][nt], a, wr[nt][kk]);
            }
        }
        __syncwarp();

#pragma unroll
        for (int mt = 0; mt < 4; mt++) {
            if (mt >= mtmax) break;
#pragma unroll
            for (int nt = 0; nt < 4; nt++) {
                int row = mt * 16 + gid, col = nt * 8 + tig * 2;
                *(float2*)&myR[row * 40 + col] = make_float2(acc[mt][nt].x, acc[mt][nt].y);
                *(float2*)&myR[(row + 8) * 40 + col] = make_float2(acc[mt][nt].z, acc[mt][nt].w);
            }
        }
        __syncthreads();

#pragma unroll
        for (int it = 0; it < 2; it++) {
            int b = cb[it], jj = cjj[it], lb = clb[it], bj = cbj[it];
            if (t < lb) {
                float gsum[4] = {0.f, 0.f, 0.f, 0.f};
#pragma unroll
                for (int w = 0; w < 8; w++) {
                    const float* pw = s + w * REGF + b * 40 + jj;
#pragma unroll
                    for (int q = 0; q < 4; q++) gsum[q] += pw[q * 8];
                }
                __half2* gp = reinterpret_cast<__half2*>(&gxp[it]);
                float2 fif = __half22float2(gp[0]);
                float2 fgo = __half22float2(gp[1]);
                float iv = gsum[0] + fif.x;
                float fv = gsum[1] + fif.y;
                float gv = gsum[2] + fgo.x;
                float ov = gsum[3] + fgo.y;
                float cn = sigm(fv) * creg[it] + sigm(iv) * tanhf(gv);
                float hn = sigm(ov) * tanhf(cn);
                creg[it] = cn;
                __half hh = __float2half_rn(hn);
                hnext16[bj] = hh;
                if (t == lb - 1) g_hout[dir][bj] = hn;
                int tout = dir ? (lb - 1 - t) : t;
                size_t xoff = (size_t)(tout * BB + b) * 1024 + dir * HH + j0 + jj;
                xo16[xoff] = hh;
                if (final) g_xf[xoff] = hn;
            } else if (t < lb + 2) {
                hnext16[bj] = hcur16[bj];
            }
        }

        __syncthreads();
        if (t < TT - 1) {
            unsigned* bar = &g_bar2[dir][0];
            if (tid == 0)
                asm volatile("red.release.gpu.global.add.u32 [%0], %1;"
                             :: "l"(bar), "r"(1u) : "memory");
            na = g_nact[t + 1];          // lands during spin
            PREFETCH_GX(t + 1)           // lands during spin
            if (tid == 0) {
                unsigned target = 64u * (unsigned)(t + 1), v;
                do {
                    asm volatile("ld.acquire.gpu.global.u32 %0, [%1];"
                                 : "=r"(v) : "l"(bar) : "memory");
                } while (v < target);
            }
            __syncthreads();
        }
    }

#pragma unroll
    for (int it = 0; it < 2; it++) g_c[dir][cbj[it]] = creg[it];
#undef PREFETCH_GX
}

extern "C" void kernel_launch(void* const* d_in, const int* in_sizes, int n_in,
                              void* d_out, int out_size) {
    const float* data   = (const float*)d_in[0];
    const float* h0     = (const float*)d_in[1];
    const float* c0     = (const float*)d_in[2];
    const float* w_ih0  = (const float*)d_in[3];
    const float* w_hh0  = (const float*)d_in[4];
    const float* b0     = (const float*)d_in[5];
    const float* w_ih_r = (const float*)d_in[6];
    const float* w_hh_r = (const float*)d_in[7];
    const float* b_r    = (const float*)d_in[8];
    const int*   pack   = (const int*)d_in[10];

    const int NP = in_sizes[0] / 512;
    float* out = (float*)d_out;

    static int smem_set = 0;
    if (!smem_set) {
        cudaFuncSetAttribute(k_scan, cudaFuncAttributeMaxDynamicSharedMemorySize, SCAN_SMEM);
        smem_set = 1;
    }

    k_len<<<1, 1024>>>(pack, NP);
    k_scatter<<<(NP * 512 + 255) / 256, 256>>>(data, pack, NP * 512);

    const int LX[3]  = {0, 1, 0};
    const int LLD[3] = {512, 1024, 1024};
    const int LK[3]  = {512, 1024, 1024};
    const int LO[3]  = {1, 0, 1};

    for (int l = 0; l < 3; l++) {
        const float* Wih = (l == 0) ? w_ih0 : w_ih_r + (size_t)(l - 1) * 2 * GG * 1024;
        int n4 = 2 * GG * LK[l] / 4;
        k_wcvt<<<(n4 + 255) / 256, 256>>>(Wih, n4);

        for (int d = 0; d < 2; d++) {
            const float* bs = (l == 0) ? b0 + (size_t)d * GG
                                       : b_r + (size_t)((l - 1) * 2 + d) * GG;
            k_gemm_gx<<<dim3(32, TB / 128), 256>>>(LX[l], LLD[l], LK[l], d, bs);
        }
        k_init<<<256, 256>>>(h0, c0, l);

        const float* W0 = (l == 0) ? w_hh0 : w_hh_r + (size_t)((l - 1) * 2 + 0) * GG * HH;
        const float* W1 = (l == 0) ? w_hh0 + (size_t)GG * HH
                                   : w_hh_r + (size_t)((l - 1) * 2 + 1) * GG * HH;
        k_scan<<<128, 256, SCAN_SMEM>>>(W0, W1, LO[l], l == 2);

        k_save<<<256, 256>>>(out, NP, l);
    }
    k_gather<<<(NP * 1024 + 255) / 256, 256>>>(out, pack, NP * 1024);
}